// round 13
// baseline (speedup 1.0000x reference)
#include <cuda_runtime.h>
#include <stdint.h>

// Problem constants (fixed by the reference)
#define B_     8192
#define W0_    1024
#define R_     8
#define G_     1024
#define WORDS  (B_ / 32)          // 256 batch words
#define OUTW   (W0_ + R_ * G_)    // 9216 output columns
#define NT     512                // threads per block

#define ONE_F  0x3F800000u        // bit pattern of 1.0f
#define STAGE_WORDS (8 * 1024)    // one staging buffer: 8 rows x 1024 cols
#define SMEM_BYTES ((OUTW + 2 * STAGE_WORDS) * 4)   // 36K bits + 64K stage = 100KB

// ---------------------------------------------------------------------------
// R10: replace ALL per-thread STG output stores with TMA bulk stores
// (cp.async.bulk shared->global). Rationale: dur/DRAM% were invariant at
// ~59us / 58% across interleaving, 2x occupancy, and prefetching, while no
// SM pipe was saturated — pointing at the per-thread STG->L1tex->L2 write
// delivery path as the ceiling (~4.65 TB/s). TMA stores bypass that path
// (SMEM -> L2 direct, LTS-cap ~6300 B/cyc path-independent).
//
// Structure per block (one batch word, 32 samples, 512 threads):
//   pack x -> smem bit state s[9216]
//   for region p = 0..8 (region 0 = x cols, region p>=1 = gate row p-1):
//     if p>=1: compute 1024 gates into s[p*1024..) (params reg-prefetched)
//     4 sub-phases, each: expand 8 batch rows x 1024 cols of region p into
//       a double-buffered smem float stage, fence.proxy.async, then threads
//       0..7 each issue one 4KB cp.async.bulk (one output batch row) +
//       commit_group; wait_group.read 1 gates staging-buffer reuse.
// ---------------------------------------------------------------------------
__global__ __launch_bounds__(NT, 2) void gator_tma_kernel(
    const float* __restrict__ x,        // [B, W0] 0/1 floats
    const float* __restrict__ gates,    // [R, G, 4]
    const int*   __restrict__ choices,  // [R, G, 2]
    float*       __restrict__ out)      // [B, OUTW]
{
    extern __shared__ uint32_t dsm[];
    uint32_t* s     = dsm;              // [OUTW] bit state
    uint32_t* stage = dsm + OUTW;       // [2][8][1024] float-as-u32 staging

    const int w    = blockIdx.x;        // batch word (32 samples)
    const int tid  = threadIdx.x;
    const int warp = tid >> 5;          // 0..15
    const int lane = tid & 31;

    const int4*   ch4 = reinterpret_cast<const int4*>(choices);  // [R*512]
    const float4* g4  = reinterpret_cast<const float4*>(gates);  // [R*1024]

    // Prefetch row 0 params (thread t owns gates 2t, 2t+1; coalesced).
    int4   ch = __ldg(ch4 + tid);
    float4 ta = __ldg(g4 + 2 * tid);
    float4 tb = __ldg(g4 + 2 * tid + 1);

    // ---- pack: x[w*32 .. w*32+31, :] -> ballot bits in s[0..1024) --------
    {
        const float4* row = reinterpret_cast<const float4*>(
            x + (size_t)(w * 32 + lane) * W0_);
        const int colbase = warp * 64;
        #pragma unroll 4
        for (int it = 0; it < 16; ++it) {
            const int c = colbase + it * 4;
            float4 v = row[c >> 2];
            uint32_t b0 = __ballot_sync(0xffffffffu, v.x > 0.5f);
            uint32_t b1 = __ballot_sync(0xffffffffu, v.y > 0.5f);
            uint32_t b2 = __ballot_sync(0xffffffffu, v.z > 0.5f);
            uint32_t b3 = __ballot_sync(0xffffffffu, v.w > 0.5f);
            if (lane == 0) {
                s[c + 0] = b0;
                s[c + 1] = b1;
                s[c + 2] = b2;
                s[c + 3] = b3;
            }
        }
    }
    __syncthreads();

    const int t6 = tid & 63;            // 0..63: column group within region
    const int rr = tid >> 6;            // 0..7 : staging row

    #pragma unroll
    for (int p = 0; p < 9; ++p) {
        // ---- gate row p-1 (writes s[p*1024 .. p*1024+1024)) --------------
        if (p >= 1) {
            int4 chn; float4 tan, tbn;
            if (p < 8) {    // prefetch row p params over compute+store phase
                chn = __ldg(ch4 + p * 512 + tid);
                tan = __ldg(g4 + p * 1024 + 2 * tid);
                tbn = __ldg(g4 + p * 1024 + 2 * tid + 1);
            }
            uint32_t o0, o1;
            {
                const uint32_t a  = s[ch.x];
                const uint32_t bb = s[ch.y];
                const uint32_t m0 = (ta.x > 0.5f) ? 0xffffffffu : 0u;
                const uint32_t m1 = (ta.y > 0.5f) ? 0xffffffffu : 0u;
                const uint32_t m2 = (ta.z > 0.5f) ? 0xffffffffu : 0u;
                const uint32_t m3 = (ta.w > 0.5f) ? 0xffffffffu : 0u;
                o0 = (m0 & ~a & ~bb) | (m1 & ~a & bb)
                   | (m2 &  a & ~bb) | (m3 &  a &  bb);
            }
            {
                const uint32_t a  = s[ch.z];
                const uint32_t bb = s[ch.w];
                const uint32_t m0 = (tb.x > 0.5f) ? 0xffffffffu : 0u;
                const uint32_t m1 = (tb.y > 0.5f) ? 0xffffffffu : 0u;
                const uint32_t m2 = (tb.z > 0.5f) ? 0xffffffffu : 0u;
                const uint32_t m3 = (tb.w > 0.5f) ? 0xffffffffu : 0u;
                o1 = (m0 & ~a & ~bb) | (m1 & ~a & bb)
                   | (m2 &  a & ~bb) | (m3 &  a &  bb);
            }
            uint2 ov; ov.x = o0; ov.y = o1;
            *reinterpret_cast<uint2*>(&s[p * 1024 + 2 * tid]) = ov;
            if (p < 8) { ch = chn; ta = tan; tb = tbn; }
            __syncthreads();
        }

        // ---- store region p via 4 staged TMA sub-phases ------------------
        const uint32_t* sp = s + p * 1024;
        #pragma unroll
        for (int sub = 0; sub < 4; ++sub) {
            const int k   = p * 4 + sub;      // global sub index (0..35)
            const int buf = sub & 1;

            // Gate staging-buffer reuse: the copy issued 2 subs ago (same
            // buffer) must have finished READING smem. Each issuing thread
            // has committed one group per sub.
            if (k >= 2 && tid < 8)
                asm volatile("cp.async.bulk.wait_group.read 1;" ::: "memory");
            __syncthreads();   // publish buffer-free to all threads

            // Expand 8 batch rows x 1024 cols into stage[buf].
            // Thread: row rr, cols {t6*4 + i*256 | i<4}. Lane-contiguous
            // LDS.128/STS.128, conflict-free. Float via integer ALU only.
            uint32_t* st = stage + buf * STAGE_WORDS + rr * 1024;
            const int bitpos = sub * 8 + rr;  // batch sample within the word
            #pragma unroll
            for (int i = 0; i < 4; ++i) {
                const int c = t6 * 4 + i * 256;
                const uint4 bv = *reinterpret_cast<const uint4*>(sp + c);
                uint4 v;
                v.x = ((bv.x >> bitpos) & 1u) * ONE_F;
                v.y = ((bv.y >> bitpos) & 1u) * ONE_F;
                v.z = ((bv.z >> bitpos) & 1u) * ONE_F;
                v.w = ((bv.w >> bitpos) & 1u) * ONE_F;
                *reinterpret_cast<uint4*>(st + c) = v;
            }
            // Make generic-proxy STS visible to the async (TMA) proxy.
            asm volatile("fence.proxy.async.shared::cta;" ::: "memory");
            __syncthreads();   // staging complete

            // Threads 0..7: one 4KB bulk store each (one output batch row,
            // contiguous in gmem). Fire-and-forget; next sub's expansion of
            // the other buffer proceeds underneath.
            if (tid < 8) {
                const uint32_t src = (uint32_t)__cvta_generic_to_shared(
                    stage + buf * STAGE_WORDS + tid * 1024);
                float* dst = out + (size_t)(w * 32 + sub * 8 + tid) * OUTW
                                 + p * 1024;
                asm volatile(
                    "cp.async.bulk.global.shared::cta.bulk_group [%0], [%1], %2;"
                    :: "l"(dst), "r"(src), "r"(4096) : "memory");
                asm volatile("cp.async.bulk.commit_group;" ::: "memory");
            }
        }
    }

    // Drain all outstanding bulk stores before exit.
    if (tid < 8)
        asm volatile("cp.async.bulk.wait_group 0;" ::: "memory");
}

// ---------------------------------------------------------------------------
// Single launch; no allocation, no sync -> graph-capturable. The attribute
// set is a host-side function-attribute call (not a stream op), fine under
// capture. Inputs (metadata order): x f32 [8192,1024], gates f32 [8,1024,4],
// choices i32 [8,1024,2]. Output f32 [8192, 9216].
// ---------------------------------------------------------------------------
extern "C" void kernel_launch(void* const* d_in, const int* in_sizes, int n_in,
                              void* d_out, int out_size) {
    const float* x       = (const float*)d_in[0];
    const float* gates   = (const float*)d_in[1];
    const int*   choices = (const int*)  d_in[2];
    float*       out     = (float*)d_out;

    cudaFuncSetAttribute(gator_tma_kernel,
                         cudaFuncAttributeMaxDynamicSharedMemorySize,
                         SMEM_BYTES);

    gator_tma_kernel<<<WORDS, NT, SMEM_BYTES>>>(x, gates, choices, out);
}

// round 14
// speedup vs baseline: 1.0655x; 1.0655x over previous
#include <cuda_runtime.h>
#include <stdint.h>

// Problem constants (fixed by the reference)
#define B_     8192
#define W0_    1024
#define R_     8
#define G_     1024
#define WORDS  (B_ / 32)          // 256 batch words
#define OUTW   (W0_ + R_ * G_)    // 9216 output columns
#define NT     512                // threads per block

#define ONE_F  0x3F800000u        // bit pattern of 1.0f

// ---------------------------------------------------------------------------
// R14: DRAM write-pattern experiment.
// All previous variants (STG interleaved, STG burst, TMA) wrote 4KB chunks at
// 36KB stride => ~8192 interleaved write streams chip-wide, and all pinned at
// ~4.6 TB/s with DRAM only ~56-58% busy — the address pattern is the one
// shared invariant. Block w's full output (batch rows w*32..w*32+31) is ONE
// contiguous 1.18MB slab. This kernel computes the whole bit state first,
// then unpacks ROW-MAJOR: each batch row is a 36KB sequential write, two rows
// in flight per block => ~512 long sequential streams chip-wide instead of
// 8192 tiny interleaved ones. Same bytes, same instruction mix; only the
// DRAM page/bank locality changes.
// ---------------------------------------------------------------------------
__global__ __launch_bounds__(NT, 2) void gator_fused_kernel(
    const float* __restrict__ x,        // [B, W0] 0/1 floats
    const float* __restrict__ gates,    // [R, G, 4]
    const int*   __restrict__ choices,  // [R, G, 2]
    float*       __restrict__ out)      // [B, OUTW]
{
    __shared__ uint32_t s[OUTW];        // 36864 bytes of bit state

    const int w    = blockIdx.x;        // batch word (32 samples)
    const int tid  = threadIdx.x;
    const int warp = tid >> 5;          // 0..15
    const int lane = tid & 31;

    const int4*   ch4 = reinterpret_cast<const int4*>(choices);  // [R*512]
    const float4* g4  = reinterpret_cast<const float4*>(gates);  // [R*1024]

    // Prefetch row 0 params (thread t owns gates 2t, 2t+1; coalesced).
    int4   ch = __ldg(ch4 + tid);
    float4 ta = __ldg(g4 + 2 * tid);
    float4 tb = __ldg(g4 + 2 * tid + 1);

    // ---- pack: x[w*32 .. w*32+31, :] -> ballot bits in s[0..1024) --------
    // Lane = sample; warp j covers columns [j*64, j*64+64). Per-lane float4
    // loads stream sequentially -> 8x L1 reuse of each 128B line.
    {
        const float4* row = reinterpret_cast<const float4*>(
            x + (size_t)(w * 32 + lane) * W0_);
        const int colbase = warp * 64;
        #pragma unroll 4
        for (int it = 0; it < 16; ++it) {
            const int c = colbase + it * 4;
            float4 v = row[c >> 2];
            uint32_t b0 = __ballot_sync(0xffffffffu, v.x > 0.5f);
            uint32_t b1 = __ballot_sync(0xffffffffu, v.y > 0.5f);
            uint32_t b2 = __ballot_sync(0xffffffffu, v.z > 0.5f);
            uint32_t b3 = __ballot_sync(0xffffffffu, v.w > 0.5f);
            if (lane == 0) {
                s[c + 0] = b0;
                s[c + 1] = b1;
                s[c + 2] = b2;
                s[c + 3] = b3;
            }
        }
    }
    __syncthreads();

    // ---- 8 gate rows in smem, params register-double-buffered ------------
    #pragma unroll
    for (int r = 0; r < R_; ++r) {
        int4 chn; float4 tan, tbn;
        if (r < R_ - 1) {   // next row's params fly over compute + barrier
            chn = __ldg(ch4 + (r + 1) * 512 + tid);
            tan = __ldg(g4 + (r + 1) * 1024 + 2 * tid);
            tbn = __ldg(g4 + (r + 1) * 1024 + 2 * tid + 1);
        }
        const int outbase = W0_ + r * G_;

        uint32_t o0, o1;
        {
            const uint32_t a  = s[ch.x];
            const uint32_t bb = s[ch.y];
            const uint32_t m0 = (ta.x > 0.5f) ? 0xffffffffu : 0u;
            const uint32_t m1 = (ta.y > 0.5f) ? 0xffffffffu : 0u;
            const uint32_t m2 = (ta.z > 0.5f) ? 0xffffffffu : 0u;
            const uint32_t m3 = (ta.w > 0.5f) ? 0xffffffffu : 0u;
            o0 = (m0 & ~a & ~bb) | (m1 & ~a & bb)
               | (m2 &  a & ~bb) | (m3 &  a &  bb);
        }
        {
            const uint32_t a  = s[ch.z];
            const uint32_t bb = s[ch.w];
            const uint32_t m0 = (tb.x > 0.5f) ? 0xffffffffu : 0u;
            const uint32_t m1 = (tb.y > 0.5f) ? 0xffffffffu : 0u;
            const uint32_t m2 = (tb.z > 0.5f) ? 0xffffffffu : 0u;
            const uint32_t m3 = (tb.w > 0.5f) ? 0xffffffffu : 0u;
            o1 = (m0 & ~a & ~bb) | (m1 & ~a & bb)
               | (m2 &  a & ~bb) | (m3 &  a &  bb);
        }
        uint2 ov; ov.x = o0; ov.y = o1;
        *reinterpret_cast<uint2*>(&s[outbase + 2 * tid]) = ov;

        ch = chn; ta = tan; tb = tbn;
        __syncthreads();
    }

    // ---- unpack: ROW-MAJOR sequential streams -----------------------------
    // Threads split in 2 groups of 256; group g handles batch row ip*2+g.
    // Thread t2 writes float4 at column-4 index t2 + 256*j, j ascending, so
    // each 36KB output row is written front-to-back; a block keeps exactly
    // 2 sequential streams live inside its contiguous 1.18MB slab.
    {
        const int g  = tid >> 8;          // 0 or 1
        const int t2 = tid & 255;
        uint32_t* oblk = reinterpret_cast<uint32_t*>(out)
                       + (size_t)(w * 32) * OUTW;

        #pragma unroll
        for (int ip = 0; ip < 16; ++ip) {
            const int row = ip * 2 + g;   // batch sample within the word
            uint4* base = reinterpret_cast<uint4*>(oblk + (size_t)row * OUTW);

            #pragma unroll
            for (int j = 0; j < 9; ++j) {
                const int c4 = t2 + 256 * j;              // 0..2303
                const uint4 bv = *reinterpret_cast<const uint4*>(&s[4 * c4]);
                uint4 v;
                v.x = ((bv.x >> row) & 1u) * ONE_F;       // integer ALU only
                v.y = ((bv.y >> row) & 1u) * ONE_F;
                v.z = ((bv.z >> row) & 1u) * ONE_F;
                v.w = ((bv.w >> row) & 1u) * ONE_F;
                __stcs(base + c4, v);
            }
        }
    }
}

// ---------------------------------------------------------------------------
// Single launch; no allocation, no sync -> graph-capturable.
// Inputs (metadata order): x f32 [8192,1024], gates f32 [8,1024,4],
// choices i32 [8,1024,2]. Output f32 [8192, 9216].
// ---------------------------------------------------------------------------
extern "C" void kernel_launch(void* const* d_in, const int* in_sizes, int n_in,
                              void* d_out, int out_size) {
    const float* x       = (const float*)d_in[0];
    const float* gates   = (const float*)d_in[1];
    const int*   choices = (const int*)  d_in[2];
    float*       out     = (float*)d_out;

    gator_fused_kernel<<<WORDS, NT>>>(x, gates, choices, out);
}